// round 11
// baseline (speedup 1.0000x reference)
#include <cuda_runtime.h>
#include <cuda_bf16.h>
#include <stdint.h>
#include <math.h>

// Problem constants
#define B      64
#define LS     256
#define MM     16
#define NSTEP  10
#define HH     1024
#define BM     1024
#define KW     512
#define NSEG   11
#define P_STRIDE (BM*HH)

#define N_SELEM (B*(NSTEP+1)*LS)     // 180224
#define NB_CHAIN 128

// GEMM tiling
#define PITCH 72                      // smem row pitch in bf16 (64 + 8 pad)
#define STAGE_ELEMS (128 * PITCH)     // per-matrix stage elems

// ---- scratch (static __device__, allocation-free) ----
__device__ float g_P[NSEG * BM * HH];
__device__ float g_W2T[NSTEP * LS * HH];
__device__ float g_WBT[NSTEP * 1024 * 512];
__device__ float g_VBT[1024 * 512];
__device__ float g_yp[NSEG * MM * HH];
__device__ float g_phi[B * LS];
__device__ float g_S[2 * LS * B];
__device__ float g_spart[B * 2048];
__device__ float g_g[B * HH];
__device__ float g_rhosum[B];

// split-bf16 GEMM operands
__device__ __nv_bfloat16 g_Abf[1024 * 1024];     // [m][k']: k'<512 hi, else lo
__device__ __nv_bfloat16 g_Wbf[11264 * 1024];    // [n][k']: k'<512 hi, else lo

// grid-barrier state
__device__ int g_arr[NB_CHAIN * 32];
__device__ int g_rel;

// slab-ready flags (GEMM -> chain overlap)
__device__ int g_slabCnt[16];
__device__ int g_slabReady[16];

__global__ void kReset() {
    int t = threadIdx.x;
    for (int i = t; i < NB_CHAIN * 32; i += 256) g_arr[i] = 0;
    if (t == 0) g_rel = 0;
}

__device__ __forceinline__ void grid_bar(int epoch) {
    __syncthreads();
    int bid = blockIdx.x, tid = threadIdx.x;
    if (bid == 0) {
        if (tid > 0 && tid < NB_CHAIN) {
            while (*(volatile int*)&g_arr[tid * 32] < epoch) {}
        }
        __syncthreads();
        if (tid == 0) { __threadfence(); *(volatile int*)&g_rel = epoch; }
    } else {
        if (tid == 0) {
            __threadfence();
            *(volatile int*)&g_arr[bid * 32] = epoch;
            while (*(volatile int*)&g_rel < epoch) {}
            __threadfence();
        }
    }
    __syncthreads();
}

__device__ __forceinline__ void write_s(float* out, int idx, float cv, float sv,
                                        int inter, int imOff) {
    if (inter) { out[2 * idx] = cv; out[2 * idx + 1] = sv; }
    else { out[idx] = cv; if (imOff >= 0) out[imOff + idx] = sv; }
}

// ============ portable async-copy helpers (sm_80+; no 'a'-suffix features) ====
__device__ __forceinline__ uint32_t smem_u32(const void* p) {
    uint32_t a;
    asm("{ .reg .u64 t; cvta.to.shared.u64 t, %1; cvt.u32.u64 %0, t; }"
        : "=r"(a) : "l"(p));
    return a;
}
__device__ __forceinline__ void cp_async16(uint32_t dst, const void* src) {
    asm volatile("cp.async.cg.shared.global [%0], [%1], 16;" :: "r"(dst), "l"(src));
}
#define CP_COMMIT() asm volatile("cp.async.commit_group;" ::: "memory")
#define CP_WAIT0()  asm volatile("cp.async.wait_group 0;" ::: "memory")
#define CP_WAIT1()  asm volatile("cp.async.wait_group 1;" ::: "memory")

__device__ __forceinline__ void mma_bf16(float& c0, float& c1, float& c2, float& c3,
                                         uint32_t a0, uint32_t a1, uint32_t a2, uint32_t a3,
                                         uint32_t b0, uint32_t b1) {
    asm volatile(
        "mma.sync.aligned.m16n8k16.row.col.f32.bf16.bf16.f32 "
        "{%0,%1,%2,%3}, {%4,%5,%6,%7}, {%8,%9}, {%0,%1,%2,%3};"
        : "+f"(c0), "+f"(c1), "+f"(c2), "+f"(c3)
        : "r"(a0), "r"(a1), "r"(a2), "r"(a3), "r"(b0), "r"(b1));
}

// ============ precompute ============

// A split: [row][k] hi, [row][512+k] lo. Also resets slab flags (block 0).
__global__ void kConvA(const float* __restrict__ wr, const float* __restrict__ wi) {
    if (blockIdx.x == 0 && threadIdx.x < 16) {
        g_slabCnt[threadIdx.x] = 0;
        g_slabReady[threadIdx.x] = 0;
    }
    int e = blockIdx.x * 256 + threadIdx.x;       // 524288
    int row = e >> 9, k = e & 511;
    int b = row >> 4, m = row & 15;
    float a = (k < 256) ? wr[((size_t)b * 256 + k) * 16 + m]
                        : wi[((size_t)b * 256 + (k - 256)) * 16 + m];
    __nv_bfloat16 hi = __float2bfloat16(a);
    __nv_bfloat16 lo = __float2bfloat16(a - __bfloat162float(hi));
    g_Abf[(size_t)row * 1024 + k] = hi;
    g_Abf[(size_t)row * 1024 + 512 + k] = lo;
}

// W split + transpose: g_Wbf[n= s*1024+h][k] = hi(W[512+k][h]), [n][512+k] = lo
__global__ void kConvW(const float* __restrict__ W1, const float* __restrict__ V1) {
    __shared__ float t[32][33];
    int s  = blockIdx.z;
    int h0 = blockIdx.x * 32;
    int k0 = blockIdx.y * 32;
    int tx = threadIdx.x, ty = threadIdx.y;   // 32 x 8
    #pragma unroll
    for (int i = 0; i < 32; i += 8) {
        int k = k0 + ty + i;
        float v = (s < NSTEP) ? W1[((size_t)s * 1280 + 512 + k) * 1024 + h0 + tx]
                              : V1[(size_t)(512 + k) * 1024 + h0 + tx];
        t[ty + i][tx] = v;
    }
    __syncthreads();
    #pragma unroll
    for (int i = 0; i < 32; i += 8) {
        size_t n = (size_t)s * 1024 + h0 + ty + i;
        float a = t[tx][ty + i];
        __nv_bfloat16 hi = __float2bfloat16(a);
        __nv_bfloat16 lo = __float2bfloat16(a - __bfloat162float(hi));
        g_Wbf[n * 1024 + k0 + tx] = hi;
        g_Wbf[n * 1024 + 512 + k0 + tx] = lo;
    }
}

__global__ void kTw2(const float* __restrict__ W2) {
    __shared__ float t[32][33];
    int s  = blockIdx.z;
    int k0 = blockIdx.x * 32, l0 = blockIdx.y * 32;
    int tx = threadIdx.x, ty = threadIdx.y;
    #pragma unroll
    for (int i = 0; i < 32; i += 8)
        t[ty + i][tx] = W2[((size_t)s * 1024 + k0 + ty + i) * 256 + l0 + tx];
    __syncthreads();
    #pragma unroll
    for (int i = 0; i < 32; i += 8)
        g_W2T[((size_t)s * 256 + l0 + ty + i) * 1024 + k0 + tx] = t[tx][ty + i];
}

__global__ void kTwb(const float* __restrict__ W1, const float* __restrict__ V1) {
    __shared__ float t[32][33];
    int s  = blockIdx.z;
    int j0 = blockIdx.x * 32;
    int k0 = blockIdx.y * 32;
    int tx = threadIdx.x, ty = threadIdx.y;
    #pragma unroll
    for (int i = 0; i < 32; i += 8) {
        int k = k0 + ty + i;
        float v = (s < NSTEP) ? W1[((size_t)s * 1280 + k) * 1024 + j0 + tx]
                              : V1[(size_t)k * 1024 + j0 + tx];
        t[ty + i][tx] = v;
    }
    __syncthreads();
    #pragma unroll
    for (int i = 0; i < 32; i += 8) {
        int j = j0 + ty + i;
        if (s < NSTEP)
            g_WBT[((size_t)s * 1024 + j) * 512 + k0 + tx] = t[tx][ty + i];
        else
            g_VBT[(size_t)j * 512 + k0 + tx] = t[tx][ty + i];
    }
}

// kY2: 512 threads, 4-way l-split for MLP; was latency-bound at occ 6%.
__global__ __launch_bounds__(512) void kY2(const float* __restrict__ yM,
                                           const float* __restrict__ W1,
                                           const float* __restrict__ V1) {
    __shared__ float sy[4096];
    __shared__ float part[4][128][16];   // 32KB
    int tx = threadIdx.x & 127, yq = threadIdx.x >> 7;
    int s = blockIdx.x;
    int h = blockIdx.y * 128 + tx;
    for (int i = threadIdx.x; i < 4096; i += 512) sy[i] = yM[i];
    __syncthreads();
    const float* base = (s < NSTEP)
        ? (W1 + ((size_t)s * 1280 + 1024) * 1024 + h)
        : (V1 + (size_t)1024 * 1024 + h);
    float acc[16];
    #pragma unroll
    for (int m = 0; m < 16; m++) acc[m] = 0.f;
    int l0 = yq * 64;
    #pragma unroll 8
    for (int l = l0; l < l0 + 64; l++) {
        float w = base[(size_t)l * 1024];
        #pragma unroll
        for (int m = 0; m < 16; m++) acc[m] += sy[l * 16 + m] * w;
    }
    #pragma unroll
    for (int m = 0; m < 16; m++) part[yq][tx][m] = acc[m];
    __syncthreads();
    if (yq == 0) {
        #pragma unroll
        for (int m = 0; m < 16; m++) {
            float v = part[0][tx][m] + part[1][tx][m] + part[2][tx][m] + part[3][tx][m];
            g_yp[((size_t)s * 16 + m) * HH + h] = v;
        }
    }
}

// ====== mma.sync split-bf16 GEMM: P = A' @ W'^T (+ yp + bias) ======
// grid (88, 8), 256 threads = 8 warps (2m x 4n), warp tile 64x32.
// Slabs processed in order 10, 0, 1, ..., 9; per-slab ready flag for chain overlap.
__global__ __launch_bounds__(256)
void kGemmT(const float* __restrict__ b1, const float* __restrict__ c1) {
    extern __shared__ __align__(16) __nv_bfloat16 sh[];   // 2 bufs x (A|B)

    int tid = threadIdx.x, wid = tid >> 5, lane = tid & 31;
    int warp_m = wid >> 2, warp_n = wid & 3;              // 2 x 4
    int sIdx = blockIdx.x >> 3;
    int slab = (sIdx == 0) ? 10 : (sIdx - 1);
    int n0 = slab * 1024 + (blockIdx.x & 7) * 128;
    int r0 = blockIdx.y * 128;
    int g = lane >> 2, t4 = lane & 3;

    const __nv_bfloat16* agp = g_Abf + (size_t)r0 * 1024;
    const __nv_bfloat16* wgp = g_Wbf + (size_t)n0 * 1024;

    float c[4][4][4];
    #pragma unroll
    for (int mi = 0; mi < 4; mi++)
        #pragma unroll
        for (int ni = 0; ni < 4; ni++)
            #pragma unroll
            for (int q = 0; q < 4; q++) c[mi][ni][q] = 0.f;

    auto load_stage = [&](int buf, int st) {
        int t2 = st >> 3, kc = st & 7;
        int aCol = ((t2 == 2) ? 512 : 0) + kc * 64;
        int wCol = ((t2 == 1) ? 512 : 0) + kc * 64;
        __nv_bfloat16* As = sh + (size_t)buf * 2 * STAGE_ELEMS;
        __nv_bfloat16* Bs = As + STAGE_ELEMS;
        #pragma unroll
        for (int r = 0; r < 4; r++) {
            int idx = tid + 256 * r;          // 0..1023
            int row = idx >> 3, c8 = idx & 7;
            cp_async16(smem_u32(As + row * PITCH + c8 * 8),
                       agp + (size_t)row * 1024 + aCol + c8 * 8);
            cp_async16(smem_u32(Bs + row * PITCH + c8 * 8),
                       wgp + (size_t)row * 1024 + wCol + c8 * 8);
        }
    };

    load_stage(0, 0);
    CP_COMMIT();

    int buf = 0;
    for (int st = 0; st < 24; st++) {
        if (st < 23) { load_stage(buf ^ 1, st + 1); CP_COMMIT(); CP_WAIT1(); }
        else         { CP_WAIT0(); }
        __syncthreads();

        const __nv_bfloat16* As = sh + (size_t)buf * 2 * STAGE_ELEMS;
        const __nv_bfloat16* Bs = As + STAGE_ELEMS;
        #pragma unroll
        for (int ks = 0; ks < 4; ks++) {
            uint32_t af[4][4], bf[4][2];
            #pragma unroll
            for (int mi = 0; mi < 4; mi++) {
                const __nv_bfloat16* ap =
                    As + (warp_m * 64 + mi * 16 + g) * PITCH + ks * 16 + 2 * t4;
                af[mi][0] = *(const uint32_t*)ap;
                af[mi][1] = *(const uint32_t*)(ap + 8 * PITCH);
                af[mi][2] = *(const uint32_t*)(ap + 8);
                af[mi][3] = *(const uint32_t*)(ap + 8 * PITCH + 8);
            }
            #pragma unroll
            for (int ni = 0; ni < 4; ni++) {
                const __nv_bfloat16* bp =
                    Bs + (warp_n * 32 + ni * 8 + g) * PITCH + ks * 16 + 2 * t4;
                bf[ni][0] = *(const uint32_t*)bp;
                bf[ni][1] = *(const uint32_t*)(bp + 8);
            }
            #pragma unroll
            for (int mi = 0; mi < 4; mi++)
                #pragma unroll
                for (int ni = 0; ni < 4; ni++)
                    mma_bf16(c[mi][ni][0], c[mi][ni][1], c[mi][ni][2], c[mi][ni][3],
                             af[mi][0], af[mi][1], af[mi][2], af[mi][3],
                             bf[ni][0], bf[ni][1]);
        }
        __syncthreads();
        buf ^= 1;
    }

    // epilogue: c[mi][ni] fragment -> g_P with yp + bias
    int s = slab, hbase = n0 & 1023;
    const float* bias = (s < NSTEP) ? (b1 + s * 1024) : c1;
    #pragma unroll
    for (int mi = 0; mi < 4; mi++) {
        int rloc0 = warp_m * 64 + mi * 16 + g;        // and +8
        #pragma unroll
        for (int ni = 0; ni < 4; ni++) {
            int col = warp_n * 32 + ni * 8 + 2 * t4;  // even
            int hg = hbase + col;
            float yb0a = g_yp[((size_t)s * 16 + (rloc0 & 15)) * 1024 + hg]     + bias[hg];
            float yb1a = g_yp[((size_t)s * 16 + (rloc0 & 15)) * 1024 + hg + 1] + bias[hg + 1];
            int rloc1 = rloc0 + 8;
            float yb0b = g_yp[((size_t)s * 16 + (rloc1 & 15)) * 1024 + hg]     + bias[hg];
            float yb1b = g_yp[((size_t)s * 16 + (rloc1 & 15)) * 1024 + hg + 1] + bias[hg + 1];
            float2 v0; v0.x = c[mi][ni][0] + yb0a; v0.y = c[mi][ni][1] + yb1a;
            float2 v1; v1.x = c[mi][ni][2] + yb0b; v1.y = c[mi][ni][3] + yb1b;
            *(float2*)(g_P + (size_t)s * P_STRIDE + (size_t)(r0 + rloc0) * 1024 + hg) = v0;
            *(float2*)(g_P + (size_t)s * P_STRIDE + (size_t)(r0 + rloc1) * 1024 + hg) = v1;
        }
    }

    // signal slab completion (64 blocks per slab)
    __threadfence();
    __syncthreads();
    if (tid == 0) {
        if (atomicAdd(&g_slabCnt[slab], 1) == 63) {
            __threadfence();
            *(volatile int*)&g_slabReady[slab] = 1;
        }
    }
}

// ============ fused sequential chain ============
__global__ __launch_bounds__(256) void kChain(
    const float* __restrict__ phi_in, const float* __restrict__ b2,
    const float* __restrict__ V2, const float* __restrict__ c2,
    float* __restrict__ out, int inter, int imOff, int rhoOff, int rhoStride)
{
    __shared__ float sw[16 * 516];
    __shared__ float shB[2048];
    __shared__ float shv2[1024];
    __shared__ float sEta[128];
    __shared__ float shpart[16];
    __shared__ float shrho[16];

    int tid = threadIdx.x, bid = blockIdx.x;
    int epoch = 0;
    #pragma unroll
    for (int i = 0; i < 4; i++) shv2[tid + 256 * i] = V2[tid + 256 * i];
    float c2v = c2[0];

    if (bid < 64) {
        int b = bid, l = tid;
        float p = phi_in[b * 256 + l];
        g_phi[b * 256 + l] = p;
        float sv, cv; sincosf(p, &sv, &cv);
        write_s(out, (b * 11) * 256 + l, cv, sv, inter, imOff);
        g_S[l * 64 + b] = cv;
        g_S[(256 + l) * 64 + b] = sv;
    }
    grid_bar(++epoch);

    for (int step = 0; step < NSTEP; step++) {
        {
            int j0 = bid * 16;
            const float* wsrc = (j0 < 1024)
                ? (g_WBT + ((size_t)step * 1024 + j0) * 512)
                : (g_VBT + (size_t)(j0 - 1024) * 512);
            #pragma unroll
            for (int r = 0; r < 8; r++) {
                int i = tid + 256 * r;
                int jj = i >> 7, kq = i & 127;
                float4 v = ((const float4*)wsrc)[i];
                *(float4*)&sw[jj * 516 + kq * 4] = v;
            }
            int jloc = tid & 15, b0 = (tid >> 4) * 4;
            int j = j0 + jloc;
            float a0 = 0.f, a1 = 0.f, a2 = 0.f, a3 = 0.f;
            const float* wrow = sw + jloc * 516;
            for (int kc = 0; kc < 16; kc++) {
                __syncthreads();
                const float4* src = (const float4*)(g_S + kc * 2048);
                ((float4*)shB)[tid]       = src[tid];
                ((float4*)shB)[tid + 256] = src[tid + 256];
                __syncthreads();
                #pragma unroll
                for (int kk = 0; kk < 32; kk++) {
                    float w = wrow[kc * 32 + kk];
                    float4 s4 = *(const float4*)&shB[kk * 64 + b0];
                    a0 += w * s4.x; a1 += w * s4.y; a2 += w * s4.z; a3 += w * s4.w;
                }
            }
            g_spart[(b0 + 0) * 2048 + j] = a0;
            g_spart[(b0 + 1) * 2048 + j] = a1;
            g_spart[(b0 + 2) * 2048 + j] = a2;
            g_spart[(b0 + 3) * 2048 + j] = a3;
        }
        grid_bar(++epoch);

        if (bid < 64) {
            int b = bid;
            // wait for P slabs (GEMM overlap); usually already set
            if (tid == 0) {
                while (*(volatile int*)&g_slabReady[10] == 0) {}
                while (*(volatile int*)&g_slabReady[step] == 0) {}
                __threadfence();
            }
            __syncthreads();
            const float4* sp4 = (const float4*)(g_spart + b * 2048);
            ((float4*)shB)[tid]       = sp4[tid];
            ((float4*)shB)[tid + 256] = sp4[tid + 256];
            __syncthreads();
            int w = tid >> 5, lane = tid & 31;
            const float* Pv = g_P + (size_t)NSTEP * P_STRIDE + (size_t)(b * 16) * HH;
            const float* rowA = Pv + (size_t)w * 1024;
            const float* rowB = Pv + (size_t)(w + 8) * 1024;
            float partA = 0.f, partB = 0.f;
            #pragma unroll 8
            for (int i = 0; i < 32; i++) {
                int h = lane + 32 * i;
                float spv = shB[1024 + h];
                float v2  = shv2[h];
                partA += fmaxf(spv + rowA[h], 0.f) * v2;
                partB += fmaxf(spv + rowB[h], 0.f) * v2;
            }
            #pragma unroll
            for (int off = 16; off > 0; off >>= 1) {
                partA += __shfl_xor_sync(0xffffffffu, partA, off);
                partB += __shfl_xor_sync(0xffffffffu, partB, off);
            }
            if (lane == 0) { shpart[w] = partA; shpart[w + 8] = partB; }
            __syncthreads();
            if (tid < 16) {
                float rho = 1.f / (1.f + expf(-(shpart[tid] + c2v)));
                shrho[tid] = rho;
                int ridx = (b * NSTEP + step) * MM + tid;
                out[rhoOff + ridx * rhoStride] = rho;
                if (rhoStride == 2) out[rhoOff + ridx * 2 + 1] = 0.f;
            }
            __syncthreads();
            if (tid == 0) {
                float rs = 0.f;
                #pragma unroll
                for (int m = 0; m < 16; m++) rs += shrho[m];
                g_rhosum[b] = rs;
            }
            const float* Ps = g_P + (size_t)step * P_STRIDE + (size_t)(b * 16) * HH;
            #pragma unroll
            for (int jj = 0; jj < 4; jj++) {
                int h = tid + 256 * jj;
                float sp1 = shB[h];
                float gacc = 0.f;
                #pragma unroll
                for (int m = 0; m < 16; m++)
                    gacc += shrho[m] * fmaxf(sp1 + Ps[(size_t)m * 1024 + h], 0.f);
                g_g[b * 1024 + h] = gacc;
            }
        }
        grid_bar(++epoch);

        {
            int l0 = bid * 2;
            const float4* wsrc = (const float4*)(g_W2T + ((size_t)step * 256 + l0) * 1024);
            ((float4*)shB)[tid]       = wsrc[tid];
            ((float4*)shB)[tid + 256] = wsrc[tid + 256];
            __syncthreads();
            int w = tid >> 5, lane = tid & 31;
            #pragma unroll
            for (int pi = 0; pi < 16; pi++) {
                int pp = w * 16 + pi;
                int lp = pp >> 6, b = pp & 63;
                const float* gr = g_g + b * 1024 + lane;
                const float* wr2 = shB + lp * 1024 + lane;
                float acc = 0.f;
                #pragma unroll
                for (int i = 0; i < 32; i++)
                    acc += wr2[32 * i] * gr[32 * i];
                #pragma unroll
                for (int off = 16; off > 0; off >>= 1)
                    acc += __shfl_xor_sync(0xffffffffu, acc, off);
                if (lane == 0) sEta[pp] = acc;
            }
            __syncthreads();
            if (tid < 128) {
                int lp = tid >> 6, b = tid & 63;
                int l = l0 + lp;
                float eta = sEta[tid] + g_rhosum[b] * b2[step * 256 + l];
                float phin = g_phi[b * 256 + l] - eta;
                g_phi[b * 256 + l] = phin;
                float sv, cv; sincosf(phin, &sv, &cv);
                write_s(out, (b * 11 + step + 1) * 256 + l, cv, sv, inter, imOff);
                g_S[l * 64 + b] = cv;
                g_S[(256 + l) * 64 + b] = sv;
            }
        }
        grid_bar(++epoch);
    }
}

// ============ launch ============
extern "C" void kernel_launch(void* const* d_in, const int* in_sizes, int n_in,
                              void* d_out, int out_size) {
    const float *phi=0,*wr=0,*wi=0,*yM=0,*W1=0,*b1=0,*W2=0,*b2=0,*V1=0,*c1=0,*V2=0,*c2=0;
    if (n_in == 12 && in_sizes[0] == 16384) {
        phi=(const float*)d_in[0]; wr=(const float*)d_in[1]; wi=(const float*)d_in[2];
        yM=(const float*)d_in[3];  W1=(const float*)d_in[4]; b1=(const float*)d_in[5];
        W2=(const float*)d_in[6];  b2=(const float*)d_in[7]; V1=(const float*)d_in[8];
        c1=(const float*)d_in[9];  V2=(const float*)d_in[10];c2=(const float*)d_in[11];
    } else {
        int seen262144 = 0, seen1024 = 0;
        for (int i = 0; i < n_in; i++) {
            const float* p = (const float*)d_in[i];
            switch (in_sizes[i]) {
                case 16384:    phi = p; break;
                case 4096:     yM  = p; break;
                case 13107200: W1  = p; break;
                case 10240:    b1  = p; break;
                case 2621440:  W2  = p; break;
                case 2560:     b2  = p; break;
                case 1310720:  V1  = p; break;
                case 1:        c2  = p; break;
                case 262144:   if (seen262144++ == 0) wr = p; else wi = p; break;
                case 1024:     if (seen1024++   == 0) c1 = p; else V2 = p; break;
                default: break;
            }
        }
    }
    float* out = (float*)d_out;

    int inter = 0, imOff = -1, rhoOff = N_SELEM, rhoStride = 1;
    if (out_size == 370688)      { imOff = N_SELEM; rhoOff = 2 * N_SELEM; }
    else if (out_size == 380928) { inter = 1; imOff = -1; rhoOff = 2 * N_SELEM; rhoStride = 2; }

    const int GEMM_SMEM = 2 * 2 * STAGE_ELEMS * (int)sizeof(__nv_bfloat16);  // 73728
    static cudaStream_t s_side = 0;
    static cudaEvent_t s_evA = 0, s_evB = 0;
    static int s_init = 0;
    if (!s_init) {
        cudaFuncSetAttribute(kGemmT, cudaFuncAttributeMaxDynamicSharedMemorySize, GEMM_SMEM);
        cudaStreamCreateWithFlags(&s_side, cudaStreamNonBlocking);
        cudaEventCreateWithFlags(&s_evA, cudaEventDisableTiming);
        cudaEventCreateWithFlags(&s_evB, cudaEventDisableTiming);
        s_init = 1;
    }

    // GEMM-path precompute first (kGemmT is the 4th launch -> ncu target)
    kConvA<<<2048, 256>>>(wr, wi);
    kConvW<<<dim3(32, 16, 11), dim3(32, 8)>>>(W1, V1);
    kY2   <<<dim3(11, 8), 512>>>(yM, W1, V1);

    // fork: GEMM runs concurrently with the remaining precompute + chain
    cudaEventRecord(s_evA, 0);
    cudaStreamWaitEvent(s_side, s_evA, 0);
    kGemmT<<<dim3(88, 8), 256, GEMM_SMEM, s_side>>>(b1, c1);

    // chain-path precompute
    kTw2<<<dim3(32, 8, 10), dim3(32, 8)>>>(W2);
    kTwb<<<dim3(32, 16, 11), dim3(32, 8)>>>(W1, V1);
    kReset<<<1, 256>>>();
    kChain<<<NB_CHAIN, 256>>>(phi, b2, V2, c2, out, inter, imOff, rhoOff, rhoStride);

    // join side stream back before capture ends
    cudaEventRecord(s_evB, s_side);
    cudaStreamWaitEvent(0, s_evB, 0);
}

// round 12
// speedup vs baseline: 1.3146x; 1.3146x over previous
#include <cuda_runtime.h>
#include <cuda_bf16.h>
#include <stdint.h>
#include <math.h>

// Problem constants
#define B      64
#define LS     256
#define MM     16
#define NSTEP  10
#define HH     1024
#define BM     1024
#define KW     512
#define NSEG   11
#define P_STRIDE (BM*HH)

#define N_SELEM (B*(NSTEP+1)*LS)     // 180224
#define NB_CHAIN 128

// GEMM tiling
#define PITCH 72                      // smem row pitch in bf16 (64 + 8 pad)
#define STAGE_ELEMS (128 * PITCH)     // per-matrix stage elems

// ---- scratch (static __device__, allocation-free) ----
__device__ float g_P[NSEG * BM * HH];
__device__ float g_W2T[NSTEP * LS * HH];
__device__ float g_WBT[NSTEP * 1024 * 512];
__device__ float g_VBT[1024 * 512];
__device__ float g_yp[NSEG * MM * HH];
__device__ float g_phi[B * LS];
__device__ float g_S[2 * LS * B];
__device__ float g_spart[B * 2048];
__device__ float g_g[B * HH];
__device__ float g_rhosum[B];

// split-bf16 GEMM operands
__device__ __nv_bfloat16 g_Abf[1024 * 1024];     // [m][k']: k'<512 hi, else lo
__device__ __nv_bfloat16 g_Wbf[11264 * 1024];    // [n][k']: k'<512 hi, else lo

// grid-barrier state
__device__ int g_arr[NB_CHAIN * 32];
__device__ int g_rel;

__global__ void kReset() {
    int t = threadIdx.x;
    for (int i = t; i < NB_CHAIN * 32; i += 256) g_arr[i] = 0;
    if (t == 0) g_rel = 0;
}

__device__ __forceinline__ void grid_bar(int epoch) {
    __syncthreads();
    int bid = blockIdx.x, tid = threadIdx.x;
    if (bid == 0) {
        if (tid > 0 && tid < NB_CHAIN) {
            while (*(volatile int*)&g_arr[tid * 32] < epoch) { __nanosleep(32); }
        }
        __syncthreads();
        if (tid == 0) { __threadfence(); *(volatile int*)&g_rel = epoch; }
    } else {
        if (tid == 0) {
            __threadfence();
            *(volatile int*)&g_arr[bid * 32] = epoch;
            while (*(volatile int*)&g_rel < epoch) { __nanosleep(32); }
            __threadfence();
        }
    }
    __syncthreads();
}

__device__ __forceinline__ void write_s(float* out, int idx, float cv, float sv,
                                        int inter, int imOff) {
    if (inter) { out[2 * idx] = cv; out[2 * idx + 1] = sv; }
    else { out[idx] = cv; if (imOff >= 0) out[imOff + idx] = sv; }
}

// ============ portable helpers (sm_80+; no 'a'-suffix features) ====
__device__ __forceinline__ uint32_t smem_u32(const void* p) {
    uint32_t a;
    asm("{ .reg .u64 t; cvta.to.shared.u64 t, %1; cvt.u32.u64 %0, t; }"
        : "=r"(a) : "l"(p));
    return a;
}
__device__ __forceinline__ void cp_async16(uint32_t dst, const void* src) {
    asm volatile("cp.async.cg.shared.global [%0], [%1], 16;" :: "r"(dst), "l"(src));
}
#define CP_COMMIT() asm volatile("cp.async.commit_group;" ::: "memory")
#define CP_WAIT0()  asm volatile("cp.async.wait_group 0;" ::: "memory")
#define CP_WAIT1()  asm volatile("cp.async.wait_group 1;" ::: "memory")

__device__ __forceinline__ void ldmatrix_x4(uint32_t& r0, uint32_t& r1,
                                            uint32_t& r2, uint32_t& r3, uint32_t addr) {
    asm volatile("ldmatrix.sync.aligned.m8n8.x4.shared.b16 {%0,%1,%2,%3}, [%4];"
                 : "=r"(r0), "=r"(r1), "=r"(r2), "=r"(r3) : "r"(addr));
}

__device__ __forceinline__ void mma_bf16(float& c0, float& c1, float& c2, float& c3,
                                         uint32_t a0, uint32_t a1, uint32_t a2, uint32_t a3,
                                         uint32_t b0, uint32_t b1) {
    asm volatile(
        "mma.sync.aligned.m16n8k16.row.col.f32.bf16.bf16.f32 "
        "{%0,%1,%2,%3}, {%4,%5,%6,%7}, {%8,%9}, {%0,%1,%2,%3};"
        : "+f"(c0), "+f"(c1), "+f"(c2), "+f"(c3)
        : "r"(a0), "r"(a1), "r"(a2), "r"(a3), "r"(b0), "r"(b1));
}

// ============ precompute ============

// A split: [row][k] hi, [row][512+k] lo
__global__ void kConvA(const float* __restrict__ wr, const float* __restrict__ wi) {
    int e = blockIdx.x * 256 + threadIdx.x;       // 524288
    int row = e >> 9, k = e & 511;
    int b = row >> 4, m = row & 15;
    float a = (k < 256) ? wr[((size_t)b * 256 + k) * 16 + m]
                        : wi[((size_t)b * 256 + (k - 256)) * 16 + m];
    __nv_bfloat16 hi = __float2bfloat16(a);
    __nv_bfloat16 lo = __float2bfloat16(a - __bfloat162float(hi));
    g_Abf[(size_t)row * 1024 + k] = hi;
    g_Abf[(size_t)row * 1024 + 512 + k] = lo;
}

// W split + transpose: g_Wbf[n= s*1024+h][k] = hi(W[512+k][h]), [n][512+k] = lo
__global__ void kConvW(const float* __restrict__ W1, const float* __restrict__ V1) {
    __shared__ float t[32][33];
    int s  = blockIdx.z;
    int h0 = blockIdx.x * 32;
    int k0 = blockIdx.y * 32;
    int tx = threadIdx.x, ty = threadIdx.y;   // 32 x 8
    #pragma unroll
    for (int i = 0; i < 32; i += 8) {
        int k = k0 + ty + i;
        float v = (s < NSTEP) ? W1[((size_t)s * 1280 + 512 + k) * 1024 + h0 + tx]
                              : V1[(size_t)(512 + k) * 1024 + h0 + tx];
        t[ty + i][tx] = v;
    }
    __syncthreads();
    #pragma unroll
    for (int i = 0; i < 32; i += 8) {
        size_t n = (size_t)s * 1024 + h0 + ty + i;
        float a = t[tx][ty + i];
        __nv_bfloat16 hi = __float2bfloat16(a);
        __nv_bfloat16 lo = __float2bfloat16(a - __bfloat162float(hi));
        g_Wbf[n * 1024 + k0 + tx] = hi;
        g_Wbf[n * 1024 + 512 + k0 + tx] = lo;
    }
}

__global__ void kTw2(const float* __restrict__ W2) {
    __shared__ float t[32][33];
    int s  = blockIdx.z;
    int k0 = blockIdx.x * 32, l0 = blockIdx.y * 32;
    int tx = threadIdx.x, ty = threadIdx.y;
    #pragma unroll
    for (int i = 0; i < 32; i += 8)
        t[ty + i][tx] = W2[((size_t)s * 1024 + k0 + ty + i) * 256 + l0 + tx];
    __syncthreads();
    #pragma unroll
    for (int i = 0; i < 32; i += 8)
        g_W2T[((size_t)s * 256 + l0 + ty + i) * 1024 + k0 + tx] = t[tx][ty + i];
}

__global__ void kTwb(const float* __restrict__ W1, const float* __restrict__ V1) {
    __shared__ float t[32][33];
    int s  = blockIdx.z;
    int j0 = blockIdx.x * 32;
    int k0 = blockIdx.y * 32;
    int tx = threadIdx.x, ty = threadIdx.y;
    #pragma unroll
    for (int i = 0; i < 32; i += 8) {
        int k = k0 + ty + i;
        float v = (s < NSTEP) ? W1[((size_t)s * 1280 + k) * 1024 + j0 + tx]
                              : V1[(size_t)k * 1024 + j0 + tx];
        t[ty + i][tx] = v;
    }
    __syncthreads();
    #pragma unroll
    for (int i = 0; i < 32; i += 8) {
        int j = j0 + ty + i;
        if (s < NSTEP)
            g_WBT[((size_t)s * 1024 + j) * 512 + k0 + tx] = t[tx][ty + i];
        else
            g_VBT[(size_t)j * 512 + k0 + tx] = t[tx][ty + i];
    }
}

// kY2: 512 threads, 4-way l-split for MLP
__global__ __launch_bounds__(512) void kY2(const float* __restrict__ yM,
                                           const float* __restrict__ W1,
                                           const float* __restrict__ V1) {
    __shared__ float sy[4096];
    __shared__ float part[4][128][16];
    int tx = threadIdx.x & 127, yq = threadIdx.x >> 7;
    int s = blockIdx.x;
    int h = blockIdx.y * 128 + tx;
    for (int i = threadIdx.x; i < 4096; i += 512) sy[i] = yM[i];
    __syncthreads();
    const float* base = (s < NSTEP)
        ? (W1 + ((size_t)s * 1280 + 1024) * 1024 + h)
        : (V1 + (size_t)1024 * 1024 + h);
    float acc[16];
    #pragma unroll
    for (int m = 0; m < 16; m++) acc[m] = 0.f;
    int l0 = yq * 64;
    #pragma unroll 8
    for (int l = l0; l < l0 + 64; l++) {
        float w = base[(size_t)l * 1024];
        #pragma unroll
        for (int m = 0; m < 16; m++) acc[m] += sy[l * 16 + m] * w;
    }
    #pragma unroll
    for (int m = 0; m < 16; m++) part[yq][tx][m] = acc[m];
    __syncthreads();
    if (yq == 0) {
        #pragma unroll
        for (int m = 0; m < 16; m++) {
            float v = part[0][tx][m] + part[1][tx][m] + part[2][tx][m] + part[3][tx][m];
            g_yp[((size_t)s * 16 + m) * HH + h] = v;
        }
    }
}

// ====== mma.sync split-bf16 GEMM with ldmatrix fragment loads ======
// grid (88, 8), 256 threads = 8 warps (2m x 4n), warp tile 64x32.
__global__ __launch_bounds__(256)
void kGemmT(const float* __restrict__ b1, const float* __restrict__ c1) {
    extern __shared__ __align__(16) __nv_bfloat16 sh[];   // 2 bufs x (A|B)

    int tid = threadIdx.x, wid = tid >> 5, lane = tid & 31;
    int warp_m = wid >> 2, warp_n = wid & 3;              // 2 x 4
    int n0 = blockIdx.x * 128;
    int r0 = blockIdx.y * 128;
    int g = lane >> 2, t4 = lane & 3;

    // ldmatrix lane-address components
    int a_row_l = warp_m * 64 + (lane & 15);              // + mi*16
    int a_col_l = (lane >> 4) << 3;                       // + ks*16
    int b_row_l = warp_n * 32 + (lane & 7) + ((lane >> 4) << 3);  // + ni*8 (ni even)
    int b_col_l = ((lane >> 3) & 1) << 3;                 // + ks*16

    const __nv_bfloat16* agp = g_Abf + (size_t)r0 * 1024;
    const __nv_bfloat16* wgp = g_Wbf + (size_t)n0 * 1024;

    float c[4][4][4];
    #pragma unroll
    for (int mi = 0; mi < 4; mi++)
        #pragma unroll
        for (int ni = 0; ni < 4; ni++)
            #pragma unroll
            for (int q = 0; q < 4; q++) c[mi][ni][q] = 0.f;

    auto load_stage = [&](int buf, int st) {
        int t2 = st >> 3, kc = st & 7;
        int aCol = ((t2 == 2) ? 512 : 0) + kc * 64;
        int wCol = ((t2 == 1) ? 512 : 0) + kc * 64;
        __nv_bfloat16* As = sh + (size_t)buf * 2 * STAGE_ELEMS;
        __nv_bfloat16* Bs = As + STAGE_ELEMS;
        #pragma unroll
        for (int r = 0; r < 4; r++) {
            int idx = tid + 256 * r;          // 0..1023
            int row = idx >> 3, c8 = idx & 7;
            cp_async16(smem_u32(As + row * PITCH + c8 * 8),
                       agp + (size_t)row * 1024 + aCol + c8 * 8);
            cp_async16(smem_u32(Bs + row * PITCH + c8 * 8),
                       wgp + (size_t)row * 1024 + wCol + c8 * 8);
        }
    };

    load_stage(0, 0);
    CP_COMMIT();

    int buf = 0;
    for (int st = 0; st < 24; st++) {
        if (st < 23) { load_stage(buf ^ 1, st + 1); CP_COMMIT(); CP_WAIT1(); }
        else         { CP_WAIT0(); }
        __syncthreads();

        const __nv_bfloat16* As = sh + (size_t)buf * 2 * STAGE_ELEMS;
        const __nv_bfloat16* Bs = As + STAGE_ELEMS;
        uint32_t aBase = smem_u32(As);
        uint32_t bBase = smem_u32(Bs);
        #pragma unroll
        for (int ks = 0; ks < 4; ks++) {
            uint32_t af[4][4], bf[4][2];
            #pragma unroll
            for (int mi = 0; mi < 4; mi++) {
                uint32_t addr = aBase +
                    ((a_row_l + mi * 16) * PITCH + ks * 16 + a_col_l) * 2;
                ldmatrix_x4(af[mi][0], af[mi][1], af[mi][2], af[mi][3], addr);
            }
            #pragma unroll
            for (int np = 0; np < 2; np++) {
                uint32_t addr = bBase +
                    ((b_row_l + np * 16) * PITCH + ks * 16 + b_col_l) * 2;
                ldmatrix_x4(bf[2 * np][0], bf[2 * np][1],
                            bf[2 * np + 1][0], bf[2 * np + 1][1], addr);
            }
            #pragma unroll
            for (int mi = 0; mi < 4; mi++)
                #pragma unroll
                for (int ni = 0; ni < 4; ni++)
                    mma_bf16(c[mi][ni][0], c[mi][ni][1], c[mi][ni][2], c[mi][ni][3],
                             af[mi][0], af[mi][1], af[mi][2], af[mi][3],
                             bf[ni][0], bf[ni][1]);
        }
        __syncthreads();
        buf ^= 1;
    }

    // epilogue
    int s = n0 >> 10, hbase = n0 & 1023;
    const float* bias = (s < NSTEP) ? (b1 + s * 1024) : c1;
    #pragma unroll
    for (int mi = 0; mi < 4; mi++) {
        int rloc0 = warp_m * 64 + mi * 16 + g;
        #pragma unroll
        for (int ni = 0; ni < 4; ni++) {
            int col = warp_n * 32 + ni * 8 + 2 * t4;
            int hg = hbase + col;
            float yb0a = g_yp[((size_t)s * 16 + (rloc0 & 15)) * 1024 + hg]     + bias[hg];
            float yb1a = g_yp[((size_t)s * 16 + (rloc0 & 15)) * 1024 + hg + 1] + bias[hg + 1];
            int rloc1 = rloc0 + 8;
            float yb0b = g_yp[((size_t)s * 16 + (rloc1 & 15)) * 1024 + hg]     + bias[hg];
            float yb1b = g_yp[((size_t)s * 16 + (rloc1 & 15)) * 1024 + hg + 1] + bias[hg + 1];
            float2 v0; v0.x = c[mi][ni][0] + yb0a; v0.y = c[mi][ni][1] + yb1a;
            float2 v1; v1.x = c[mi][ni][2] + yb0b; v1.y = c[mi][ni][3] + yb1b;
            *(float2*)(g_P + (size_t)s * P_STRIDE + (size_t)(r0 + rloc0) * 1024 + hg) = v0;
            *(float2*)(g_P + (size_t)s * P_STRIDE + (size_t)(r0 + rloc1) * 1024 + hg) = v1;
        }
    }
}

// ============ fused sequential chain (round-10 serial version) ============
__global__ __launch_bounds__(256) void kChain(
    const float* __restrict__ phi_in, const float* __restrict__ b2,
    const float* __restrict__ V2, const float* __restrict__ c2,
    float* __restrict__ out, int inter, int imOff, int rhoOff, int rhoStride)
{
    __shared__ float sw[16 * 516];
    __shared__ float shB[2048];
    __shared__ float shv2[1024];
    __shared__ float sEta[128];
    __shared__ float shpart[16];
    __shared__ float shrho[16];

    int tid = threadIdx.x, bid = blockIdx.x;
    int epoch = 0;
    #pragma unroll
    for (int i = 0; i < 4; i++) shv2[tid + 256 * i] = V2[tid + 256 * i];
    float c2v = c2[0];

    if (bid < 64) {
        int b = bid, l = tid;
        float p = phi_in[b * 256 + l];
        g_phi[b * 256 + l] = p;
        float sv, cv; sincosf(p, &sv, &cv);
        write_s(out, (b * 11) * 256 + l, cv, sv, inter, imOff);
        g_S[l * 64 + b] = cv;
        g_S[(256 + l) * 64 + b] = sv;
    }
    grid_bar(++epoch);

    for (int step = 0; step < NSTEP; step++) {
        {
            int j0 = bid * 16;
            const float* wsrc = (j0 < 1024)
                ? (g_WBT + ((size_t)step * 1024 + j0) * 512)
                : (g_VBT + (size_t)(j0 - 1024) * 512);
            #pragma unroll
            for (int r = 0; r < 8; r++) {
                int i = tid + 256 * r;
                int jj = i >> 7, kq = i & 127;
                float4 v = ((const float4*)wsrc)[i];
                *(float4*)&sw[jj * 516 + kq * 4] = v;
            }
            int jloc = tid & 15, b0 = (tid >> 4) * 4;
            int j = j0 + jloc;
            float a0 = 0.f, a1 = 0.f, a2 = 0.f, a3 = 0.f;
            const float* wrow = sw + jloc * 516;
            for (int kc = 0; kc < 16; kc++) {
                __syncthreads();
                const float4* src = (const float4*)(g_S + kc * 2048);
                ((float4*)shB)[tid]       = src[tid];
                ((float4*)shB)[tid + 256] = src[tid + 256];
                __syncthreads();
                #pragma unroll
                for (int kk = 0; kk < 32; kk++) {
                    float w = wrow[kc * 32 + kk];
                    float4 s4 = *(const float4*)&shB[kk * 64 + b0];
                    a0 += w * s4.x; a1 += w * s4.y; a2 += w * s4.z; a3 += w * s4.w;
                }
            }
            g_spart[(b0 + 0) * 2048 + j] = a0;
            g_spart[(b0 + 1) * 2048 + j] = a1;
            g_spart[(b0 + 2) * 2048 + j] = a2;
            g_spart[(b0 + 3) * 2048 + j] = a3;
        }
        grid_bar(++epoch);

        if (bid < 64) {
            int b = bid;
            const float4* sp4 = (const float4*)(g_spart + b * 2048);
            ((float4*)shB)[tid]       = sp4[tid];
            ((float4*)shB)[tid + 256] = sp4[tid + 256];
            __syncthreads();
            int w = tid >> 5, lane = tid & 31;
            const float* Pv = g_P + (size_t)NSTEP * P_STRIDE + (size_t)(b * 16) * HH;
            const float* rowA = Pv + (size_t)w * 1024;
            const float* rowB = Pv + (size_t)(w + 8) * 1024;
            float partA = 0.f, partB = 0.f;
            #pragma unroll 8
            for (int i = 0; i < 32; i++) {
                int h = lane + 32 * i;
                float spv = shB[1024 + h];
                float v2  = shv2[h];
                partA += fmaxf(spv + rowA[h], 0.f) * v2;
                partB += fmaxf(spv + rowB[h], 0.f) * v2;
            }
            #pragma unroll
            for (int off = 16; off > 0; off >>= 1) {
                partA += __shfl_xor_sync(0xffffffffu, partA, off);
                partB += __shfl_xor_sync(0xffffffffu, partB, off);
            }
            if (lane == 0) { shpart[w] = partA; shpart[w + 8] = partB; }
            __syncthreads();
            if (tid < 16) {
                float rho = 1.f / (1.f + expf(-(shpart[tid] + c2v)));
                shrho[tid] = rho;
                int ridx = (b * NSTEP + step) * MM + tid;
                out[rhoOff + ridx * rhoStride] = rho;
                if (rhoStride == 2) out[rhoOff + ridx * 2 + 1] = 0.f;
            }
            __syncthreads();
            if (tid == 0) {
                float rs = 0.f;
                #pragma unroll
                for (int m = 0; m < 16; m++) rs += shrho[m];
                g_rhosum[b] = rs;
            }
            const float* Ps = g_P + (size_t)step * P_STRIDE + (size_t)(b * 16) * HH;
            #pragma unroll
            for (int jj = 0; jj < 4; jj++) {
                int h = tid + 256 * jj;
                float sp1 = shB[h];
                float gacc = 0.f;
                #pragma unroll
                for (int m = 0; m < 16; m++)
                    gacc += shrho[m] * fmaxf(sp1 + Ps[(size_t)m * 1024 + h], 0.f);
                g_g[b * 1024 + h] = gacc;
            }
        }
        grid_bar(++epoch);

        {
            int l0 = bid * 2;
            const float4* wsrc = (const float4*)(g_W2T + ((size_t)step * 256 + l0) * 1024);
            ((float4*)shB)[tid]       = wsrc[tid];
            ((float4*)shB)[tid + 256] = wsrc[tid + 256];
            __syncthreads();
            int w = tid >> 5, lane = tid & 31;
            #pragma unroll
            for (int pi = 0; pi < 16; pi++) {
                int pp = w * 16 + pi;
                int lp = pp >> 6, b = pp & 63;
                const float* gr = g_g + b * 1024 + lane;
                const float* wr2 = shB + lp * 1024 + lane;
                float acc = 0.f;
                #pragma unroll
                for (int i = 0; i < 32; i++)
                    acc += wr2[32 * i] * gr[32 * i];
                #pragma unroll
                for (int off = 16; off > 0; off >>= 1)
                    acc += __shfl_xor_sync(0xffffffffu, acc, off);
                if (lane == 0) sEta[pp] = acc;
            }
            __syncthreads();
            if (tid < 128) {
                int lp = tid >> 6, b = tid & 63;
                int l = l0 + lp;
                float eta = sEta[tid] + g_rhosum[b] * b2[step * 256 + l];
                float phin = g_phi[b * 256 + l] - eta;
                g_phi[b * 256 + l] = phin;
                float sv, cv; sincosf(phin, &sv, &cv);
                write_s(out, (b * 11 + step + 1) * 256 + l, cv, sv, inter, imOff);
                g_S[l * 64 + b] = cv;
                g_S[(256 + l) * 64 + b] = sv;
            }
        }
        grid_bar(++epoch);
    }
}

// ============ launch ============
extern "C" void kernel_launch(void* const* d_in, const int* in_sizes, int n_in,
                              void* d_out, int out_size) {
    const float *phi=0,*wr=0,*wi=0,*yM=0,*W1=0,*b1=0,*W2=0,*b2=0,*V1=0,*c1=0,*V2=0,*c2=0;
    if (n_in == 12 && in_sizes[0] == 16384) {
        phi=(const float*)d_in[0]; wr=(const float*)d_in[1]; wi=(const float*)d_in[2];
        yM=(const float*)d_in[3];  W1=(const float*)d_in[4]; b1=(const float*)d_in[5];
        W2=(const float*)d_in[6];  b2=(const float*)d_in[7]; V1=(const float*)d_in[8];
        c1=(const float*)d_in[9];  V2=(const float*)d_in[10];c2=(const float*)d_in[11];
    } else {
        int seen262144 = 0, seen1024 = 0;
        for (int i = 0; i < n_in; i++) {
            const float* p = (const float*)d_in[i];
            switch (in_sizes[i]) {
                case 16384:    phi = p; break;
                case 4096:     yM  = p; break;
                case 13107200: W1  = p; break;
                case 10240:    b1  = p; break;
                case 2621440:  W2  = p; break;
                case 2560:     b2  = p; break;
                case 1310720:  V1  = p; break;
                case 1:        c2  = p; break;
                case 262144:   if (seen262144++ == 0) wr = p; else wi = p; break;
                case 1024:     if (seen1024++   == 0) c1 = p; else V2 = p; break;
                default: break;
            }
        }
    }
    float* out = (float*)d_out;

    int inter = 0, imOff = -1, rhoOff = N_SELEM, rhoStride = 1;
    if (out_size == 370688)      { imOff = N_SELEM; rhoOff = 2 * N_SELEM; }
    else if (out_size == 380928) { inter = 1; imOff = -1; rhoOff = 2 * N_SELEM; rhoStride = 2; }

    const int GEMM_SMEM = 2 * 2 * STAGE_ELEMS * (int)sizeof(__nv_bfloat16);  // 73728
    static int s_init = 0;
    if (!s_init) {
        cudaFuncSetAttribute(kGemmT, cudaFuncAttributeMaxDynamicSharedMemorySize, GEMM_SMEM);
        s_init = 1;
    }

    // serial schedule (kGemmT is the 4th launch -> ncu target)
    kConvA<<<2048, 256>>>(wr, wi);
    kConvW<<<dim3(32, 16, 11), dim3(32, 8)>>>(W1, V1);
    kY2   <<<dim3(11, 8), 512>>>(yM, W1, V1);
    kGemmT<<<dim3(88, 8), 256, GEMM_SMEM>>>(b1, c1);
    kTw2  <<<dim3(32, 8, 10), dim3(32, 8)>>>(W2);
    kTwb  <<<dim3(32, 16, 11), dim3(32, 8)>>>(W1, V1);
    kReset<<<1, 256>>>();
    kChain<<<NB_CHAIN, 256>>>(phi, b2, V2, c2, out, inter, imOff, rhoOff, rhoStride);
}